// round 4
// baseline (speedup 1.0000x reference)
#include <cuda_runtime.h>
#include <math.h>

// Problem constants (fixed by the dataset)
#define NGB 16          // graphs
#define NN  2048        // nodes per graph
#define NTT 32768       // total nodes
#define CIN 64
#define HID 128
#define KC  32
#define EDG 524288      // total edges
#define EPG 32768       // edges per graph
#define GN_EPS 1e-5f
#define SELU_SCALE 1.0507009873554805f
#define SELU_ALPHA 1.6732632423543772f

// ---------------- scratch (device globals; no allocation allowed) ----------------
__device__ __align__(16) float g_sum[NGB * CIN];
__device__ __align__(16) float g_sumsq[NGB * CIN];
__device__ int   g_indeg[NTT];                 // in-degree (excl self loop)
__device__ int   g_odeg[NTT];                  // out-degree (adj degrees)
__device__ int   g_rowptr[NTT];                // CSR row start (by dst)
__device__ int   g_cursor[NTT];                // scatter cursors
__device__ int   g_csrsrc[EDG];                // CSR: src node per slot
__device__ int   g_bsum[128];                  // scan block sums
__device__ int   g_boff[128];                  // scan block offsets
__device__ __align__(16) float g_dinv[NTT];
__device__ __align__(16) float g_hn[NTT * CIN];   // dinv * graphnorm(x)   (64-wide)
__device__ __align__(16) float g_agg[NTT * CIN];  // dinv_d * (sum hn_src + hn_d)
__device__ __align__(16) float g_xd[NTT * HID];   // selu(agg @ w1 + b1)
__device__ __align__(16) float g_s[NTT * KC];     // aligned copy of s
__device__ float g_tr[NGB];                       // trace(out_adj)
__device__ float g_ca[NGB * KC];
__device__ float g_cs[NGB * KC];
__device__ __align__(16) float g_ss[NGB * KC * KC];
__device__ __align__(16) float g_outacc[NGB * KC * HID];

__device__ __forceinline__ float selu_f(float v) {
    return v > 0.f ? SELU_SCALE * v : SELU_SCALE * SELU_ALPHA * (expf(v) - 1.f);
}

// ---------------- kernels ----------------

__global__ void zero_k() {
    int i = blockIdx.x * blockDim.x + threadIdx.x;
    int stride = gridDim.x * blockDim.x;
    for (int j = i; j < NTT; j += stride) { g_indeg[j] = 0; g_odeg[j] = 0; }
    for (int j = i; j < NGB * KC * HID; j += stride) g_outacc[j] = 0.f;
    for (int j = i; j < NGB * KC * KC; j += stride) g_ss[j] = 0.f;
    for (int j = i; j < NGB * CIN; j += stride) { g_sum[j] = 0.f; g_sumsq[j] = 0.f; }
    for (int j = i; j < NGB * KC; j += stride) { g_ca[j] = 0.f; g_cs[j] = 0.f; }
    for (int j = i; j < NGB; j += stride) g_tr[j] = 0.f;
}

// per-graph sum & sumsq per channel. grid = NGB*8 blocks of 512.
__global__ void __launch_bounds__(512) gn_stats_k(const float* __restrict__ x) {
    int g = blockIdx.x >> 3;
    int part = blockIdx.x & 7;           // 256 rows per part
    int t = threadIdx.x;
    int c = t & 63, rp = t >> 6;         // 8 row-phases
    float s = 0.f, q = 0.f;
    const float* xb = x + (size_t)g * NN * CIN;
    int r0 = part * 256;
    for (int r = r0 + rp; r < r0 + 256; r += 8) {
        float v = xb[r * CIN + c];
        s += v; q += v * v;
    }
    __shared__ float sh[2][8][64];
    sh[0][rp][c] = s; sh[1][rp][c] = q;
    __syncthreads();
    if (t < 64) {
        float ss = 0.f, qq = 0.f;
#pragma unroll
        for (int i = 0; i < 8; i++) { ss += sh[0][i][t]; qq += sh[1][i][t]; }
        atomicAdd(&g_sum[g * 64 + t], ss);
        atomicAdd(&g_sumsq[g * 64 + t], qq);
    }
}

// degree histograms via per-graph shared histos (src/dst are within-graph).
// grid = 64 blocks (4 per graph, 8192 edges each), 256 threads.
__global__ void __launch_bounds__(256) deg_hist_k(const int* __restrict__ ei) {
    __shared__ int hin[NN], hout[NN];
    int t = threadIdx.x;
    int g = blockIdx.x >> 2;
    int sub = blockIdx.x & 3;
    for (int i = t; i < NN; i += 256) { hin[i] = 0; hout[i] = 0; }
    __syncthreads();
    int e0 = g * EPG + sub * (EPG / 4);
    for (int i = t; i < EPG / 4; i += 256) {
        int e = e0 + i;
        atomicAdd(&hout[ei[e] & (NN - 1)], 1);
        atomicAdd(&hin[ei[EDG + e] & (NN - 1)], 1);
    }
    __syncthreads();
    int base = g * NN;
    for (int i = t; i < NN; i += 256) {
        int a = hin[i], b = hout[i];
        if (a) atomicAdd(&g_indeg[base + i], a);
        if (b) atomicAdd(&g_odeg[base + i], b);
    }
}

// ---- hierarchical exclusive scan of g_indeg (32768 = 128 blocks x 256) ----

__global__ void __launch_bounds__(256) scan1_k() {
    int b = blockIdx.x, t = threadIdx.x;
    int i = b * 256 + t;
    int v = g_indeg[i];
    int lane = t & 31, wp = t >> 5;
    int x = v;
#pragma unroll
    for (int o = 1; o < 32; o <<= 1) {
        int y = __shfl_up_sync(0xffffffffu, x, o);
        if (lane >= o) x += y;
    }
    __shared__ int ws[8];
    if (lane == 31) ws[wp] = x;
    __syncthreads();
    if (t == 0) {
        int run = 0;
#pragma unroll
        for (int w = 0; w < 8; w++) { int tmp = ws[w]; ws[w] = run; run += tmp; }
        g_bsum[b] = run;
    }
    __syncthreads();
    g_rowptr[i] = x - v + ws[wp];   // local exclusive prefix
}

__global__ void __launch_bounds__(128) scan2_k() {
    int t = threadIdx.x;
    __shared__ int sh[128];
    int v = g_bsum[t];
    sh[t] = v;
    __syncthreads();
    for (int o = 1; o < 128; o <<= 1) {
        int y = (t >= o) ? sh[t - o] : 0;
        __syncthreads();
        sh[t] += y;
        __syncthreads();
    }
    g_boff[t] = sh[t] - v;
}

__global__ void __launch_bounds__(256) scan3_k() {
    int b = blockIdx.x, t = threadIdx.x;
    int i = b * 256 + t;
    int rp = g_rowptr[i] + g_boff[b];
    g_rowptr[i] = rp;
    g_cursor[i] = rp;
    g_dinv[i] = rsqrtf((float)g_indeg[i] + 1.f);   // +1 self loop
}

// CSR scatter: slot = cursor[dst]++, csrsrc[slot] = src
__global__ void csr_scatter_k(const int* __restrict__ ei) {
    int e = blockIdx.x * blockDim.x + threadIdx.x;
    if (e < EDG) {
        int src = ei[e], dst = ei[EDG + e];
        int pos = atomicAdd(&g_cursor[dst], 1);
        g_csrsrc[pos] = src;
    }
}

// hn = dinv * graphnorm(x)  (elementwise, float4 over NTT*64)
__global__ void __launch_bounds__(256) hn_k(
    const float* __restrict__ x, const float* __restrict__ gw,
    const float* __restrict__ gb, const float* __restrict__ gms)
{
    int i = blockIdx.x * blockDim.x + threadIdx.x;   // float4 index
    if (i >= NTT * (CIN / 4)) return;
    int node = i >> 4;
    int g = node >> 11;
    int c4 = i & 15;
    float4 xv = ((const float4*)x)[i];
    float4 sm = ((const float4*)(g_sum + g * CIN))[c4];
    float4 sq = ((const float4*)(g_sumsq + g * CIN))[c4];
    float4 al = ((const float4*)gms)[c4];
    float4 wv = ((const float4*)gw)[c4];
    float4 bv = ((const float4*)gb)[c4];
    float dd = g_dinv[node];
    float4 r;
    {
        float mean = sm.x * (1.f / NN);
        float var = sq.x * (1.f / NN) - (2.f * al.x - al.x * al.x) * mean * mean;
        r.x = dd * ((xv.x - al.x * mean) * (wv.x * rsqrtf(var + GN_EPS)) + bv.x);
    }
    {
        float mean = sm.y * (1.f / NN);
        float var = sq.y * (1.f / NN) - (2.f * al.y - al.y * al.y) * mean * mean;
        r.y = dd * ((xv.y - al.y * mean) * (wv.y * rsqrtf(var + GN_EPS)) + bv.y);
    }
    {
        float mean = sm.z * (1.f / NN);
        float var = sq.z * (1.f / NN) - (2.f * al.z - al.z * al.z) * mean * mean;
        r.z = dd * ((xv.z - al.z * mean) * (wv.z * rsqrtf(var + GN_EPS)) + bv.z);
    }
    {
        float mean = sm.w * (1.f / NN);
        float var = sq.w * (1.f / NN) - (2.f * al.w - al.w * al.w) * mean * mean;
        r.w = dd * ((xv.w - al.w * mean) * (wv.w * rsqrtf(var + GN_EPS)) + bv.w);
    }
    ((float4*)g_hn)[i] = r;
}

// CSR gather on 64-wide hn rows: agg[d] = dinv_d * (hn[d] + sum_{s in N(d)} hn[s])
// warp per dst row, lane = 2 channels (float2). grid 1024 x 256.
__global__ void __launch_bounds__(256) gather_k() {
    int t = threadIdx.x, wp = t >> 5, l = t & 31;
    const float2* hn2 = (const float2*)g_hn;
    for (int row = blockIdx.x * 8 + wp; row < NTT; row += gridDim.x * 8) {
        float dd = g_dinv[row];
        float2 acc = hn2[(size_t)row * 32 + l];   // self loop term
        int start = g_rowptr[row], cnt = g_indeg[row];
        for (int base = 0; base < cnt; base += 32) {
            int n = min(32, cnt - base);
            int idx_l = (base + l < cnt) ? g_csrsrc[start + base + l] : 0;
            for (int i = 0; i < n; i++) {
                int s = __shfl_sync(0xffffffffu, idx_l, i);
                float2 v = hn2[(size_t)s * 32 + l];
                acc.x += v.x; acc.y += v.y;
            }
        }
        acc.x *= dd; acc.y *= dd;
        ((float2*)g_agg)[(size_t)row * 32 + l] = acc;
    }
}

// xd = selu(agg @ w1 + b1).  128 threads, 16-row tiles, grid-stride.
__global__ void __launch_bounds__(128) gemm1_k(
    const float* __restrict__ w1, const float* __restrict__ b1)
{
    __shared__ float w1t[128 * 66];   // 33.8 KB, w1t[j][c] = w1[c][j]
    __shared__ float aggs[16 * 64];   // 4 KB
    int t = threadIdx.x;
    for (int c = 0; c < CIN; c++) w1t[t * 66 + c] = w1[c * HID + t];
    float b1t = b1[t];
    for (int tile = blockIdx.x; tile < NTT / 16; tile += gridDim.x) {
        int row0 = tile * 16;
        __syncthreads();
        const float4* ga = ((const float4*)g_agg) + (size_t)row0 * 16;
        ((float4*)aggs)[t] = ga[t];
        ((float4*)aggs)[t + 128] = ga[t + 128];
        __syncthreads();
#pragma unroll
        for (int p = 0; p < 2; p++) {
            float acc[8];
#pragma unroll
            for (int r = 0; r < 8; r++) acc[r] = 0.f;
            for (int c = 0; c < CIN; c += 2) {
                float2 w = *(const float2*)&w1t[t * 66 + c];
#pragma unroll
                for (int r = 0; r < 8; r++) {
                    float2 h = *(const float2*)&aggs[(p * 8 + r) * 64 + c];
                    acc[r] += w.x * h.x + w.y * h.y;
                }
            }
#pragma unroll
            for (int r = 0; r < 8; r++)
                g_xd[(size_t)(row0 + p * 8 + r) * HID + t] = selu_f(acc[r] + b1t);
        }
    }
}

__device__ __forceinline__ void softmax_write(float z, int row, int k, float* __restrict__ s_out) {
    float mx = z;
#pragma unroll
    for (int o = 16; o; o >>= 1) mx = fmaxf(mx, __shfl_xor_sync(0xffffffffu, mx, o));
    float ez = expf(z - mx);
    float sm = ez;
#pragma unroll
    for (int o = 16; o; o >>= 1) sm += __shfl_xor_sync(0xffffffffu, sm, o);
    float sv = ez / sm;
    s_out[(size_t)row * KC + k] = sv;
    g_s[(size_t)row * KC + k] = sv;
}

// s = softmax(xd @ w2 + b2).  warp handles 4 rows; lane = cluster k.
__global__ void __launch_bounds__(256) sm_k(
    const float* __restrict__ w2, const float* __restrict__ b2, float* __restrict__ s_out)
{
    __shared__ float w2s[HID * KC];   // 16 KB, raw layout w2s[j*32+k]
    int t = threadIdx.x, wp = t >> 5, k = t & 31;
    for (int i = t; i < HID * KC; i += 256) w2s[i] = w2[i];
    __syncthreads();
    float b2k = b2[k];
    for (int r0 = (blockIdx.x * 8 + wp) * 4; r0 < NTT; r0 += gridDim.x * 32) {
        const float* xr = g_xd + (size_t)r0 * HID;
        float z0 = b2k, z1 = b2k, z2 = b2k, z3 = b2k;
#pragma unroll
        for (int j = 0; j < HID; j += 4) {
            float4 x0 = *(const float4*)(xr + j);
            float4 x1 = *(const float4*)(xr + HID + j);
            float4 x2 = *(const float4*)(xr + 2 * HID + j);
            float4 x3 = *(const float4*)(xr + 3 * HID + j);
            float wa = w2s[j * 32 + k];
            float wb = w2s[(j + 1) * 32 + k];
            float wc = w2s[(j + 2) * 32 + k];
            float wd = w2s[(j + 3) * 32 + k];
            z0 += x0.x * wa + x0.y * wb + x0.z * wc + x0.w * wd;
            z1 += x1.x * wa + x1.y * wb + x1.z * wc + x1.w * wd;
            z2 += x2.x * wa + x2.y * wb + x2.z * wc + x2.w * wd;
            z3 += x3.x * wa + x3.y * wb + x3.z * wc + x3.w * wd;
        }
        softmax_write(z0, r0, k, s_out);
        softmax_write(z1, r0 + 1, k, s_out);
        softmax_write(z2, r0 + 2, k, s_out);
        softmax_write(z3, r0 + 3, k, s_out);
    }
}

// per-graph reductions: out = s^T xd, ss = s^T s, ca = s^T deg, cs = s^T 1
// grid = 16 graphs * 16 chunks (128 nodes each), 512 threads
__global__ void __launch_bounds__(512) pool_k() {
    int g = blockIdx.x >> 4;
    int chunk = blockIdx.x & 15;
    int node0 = g * NN + chunk * 128;
    __shared__ float ssh[128 * 32];   // 16 KB
    __shared__ float dsh[128];
    int t = threadIdx.x;
    float4* ssh4 = (float4*)ssh;
    const float4* gs4 = (const float4*)g_s;
    for (int i = t; i < 128 * 8; i += 512) ssh4[i] = gs4[(size_t)node0 * 8 + i];
    if (t < 128) dsh[t] = (float)g_odeg[node0 + t];
    __syncthreads();

    int f = t & 127, kb = t >> 7;      // kb in 0..3 -> k = kb*8 .. kb*8+7
    int k1a = t >> 5;                  // 0..15
    int k2 = t & 31;
    float acc[8];
#pragma unroll
    for (int j = 0; j < 8; j++) acc[j] = 0.f;
    float ss0 = 0.f, ss1 = 0.f, csacc = 0.f, caacc = 0.f;

    for (int n = 0; n < 128; n++) {
        float xvv = g_xd[(size_t)(node0 + n) * HID + f];
        float4 s0 = ssh4[n * 8 + kb * 2];
        float4 s1 = ssh4[n * 8 + kb * 2 + 1];
        acc[0] += s0.x * xvv; acc[1] += s0.y * xvv; acc[2] += s0.z * xvv; acc[3] += s0.w * xvv;
        acc[4] += s1.x * xvv; acc[5] += s1.y * xvv; acc[6] += s1.z * xvv; acc[7] += s1.w * xvv;
        float sv2 = ssh[n * 32 + k2];
        ss0 += ssh[n * 32 + k1a] * sv2;
        ss1 += ssh[n * 32 + k1a + 16] * sv2;
        if (t < 32) { float sv = ssh[n * 32 + t]; csacc += sv; caacc += sv * dsh[n]; }
    }

    float* oa = g_outacc + (size_t)g * KC * HID;
#pragma unroll
    for (int j = 0; j < 8; j++) atomicAdd(&oa[(kb * 8 + j) * HID + f], acc[j]);
    atomicAdd(&g_ss[g * 1024 + t], ss0);          // cell t: (t>>5, t&31)
    atomicAdd(&g_ss[g * 1024 + t + 512], ss1);
    if (t < 32) {
        atomicAdd(&g_cs[g * 32 + t], csacc);
        atomicAdd(&g_ca[g * 32 + t], caacc);
    }
}

// trace(out_adj)[b] via CSR: tr += s[dst] . sum_{src in N(dst)} s[src]
// warp per dst row, lane = cluster channel.
__global__ void __launch_bounds__(256) trace_k() {
    int t = threadIdx.x, wp = t >> 5, l = t & 31;
    for (int row = blockIdx.x * 8 + wp; row < NTT; row += gridDim.x * 8) {
        float sv = g_s[(size_t)row * KC + l];
        float acc = 0.f;
        int start = g_rowptr[row], cnt = g_indeg[row];
        for (int base = 0; base < cnt; base += 32) {
            int n = min(32, cnt - base);
            int idx_l = (base + l < cnt) ? g_csrsrc[start + base + l] : 0;
            for (int i = 0; i < n; i++) {
                int s = __shfl_sync(0xffffffffu, idx_l, i);
                acc += g_s[(size_t)s * KC + l];
            }
        }
        float d = acc * sv;
#pragma unroll
        for (int o = 16; o; o >>= 1) d += __shfl_xor_sync(0xffffffffu, d, o);
        if (l == 0) atomicAdd(&g_tr[row >> 11], d);
    }
}

// log_softmax(selu(outacc)) over F=128.  grid 512 (b,k) rows, 128 threads.
__global__ void __launch_bounds__(128) out_final_k(float* __restrict__ outp) {
    int r = blockIdx.x;
    int t = threadIdx.x;
    __shared__ float shm[4], shs[4];
    float y = selu_f(g_outacc[(size_t)r * HID + t]);
    float mx = y;
#pragma unroll
    for (int o = 16; o; o >>= 1) mx = fmaxf(mx, __shfl_xor_sync(0xffffffffu, mx, o));
    if ((t & 31) == 0) shm[t >> 5] = mx;
    __syncthreads();
    float mall = fmaxf(fmaxf(shm[0], shm[1]), fmaxf(shm[2], shm[3]));
    float e = expf(y - mall);
    float sm = e;
#pragma unroll
    for (int o = 16; o; o >>= 1) sm += __shfl_xor_sync(0xffffffffu, sm, o);
    if ((t & 31) == 0) shs[t >> 5] = sm;
    __syncthreads();
    float tot = shs[0] + shs[1] + shs[2] + shs[3];
    outp[(size_t)r * HID + t] = y - mall - logf(tot);
}

// scalar loss.  1 block, 16 warps (warp per graph).
__global__ void __launch_bounds__(512) loss_k(float* __restrict__ outp) {
    int w = threadIdx.x >> 5, l = threadIdx.x & 31;
    __shared__ float parts[16];
    // m = 0.5 * sum(out-degrees)
    float dsum = 0.f;
    for (int n = l; n < NN; n += 32) dsum += (float)g_odeg[w * NN + n];
#pragma unroll
    for (int o = 16; o; o >>= 1) dsum += __shfl_xor_sync(0xffffffffu, dsum, o);
    float m = 0.5f * dsum;

    // spectral
    float ca = g_ca[w * 32 + l];
    float cn = ca * ca;
#pragma unroll
    for (int o = 16; o; o >>= 1) cn += __shfl_xor_sync(0xffffffffu, cn, o);
    float norm_tr = cn / (2.f * m);
    float spec = -(g_tr[w] - norm_tr) / (2.f * m);

    // ortho: sqrt(2 - 2*tr(ss)/(||ss||_F * sqrt(K)))
    float sq = 0.f;
    for (int i = l; i < KC * KC; i += 32) { float v = g_ss[w * 1024 + i]; sq += v * v; }
#pragma unroll
    for (int o = 16; o; o >>= 1) sq += __shfl_xor_sync(0xffffffffu, sq, o);
    float fro = sqrtf(sq);
    float dtr = g_ss[w * 1024 + l * 33];   // diag element l
#pragma unroll
    for (int o = 16; o; o >>= 1) dtr += __shfl_xor_sync(0xffffffffu, dtr, o);
    float ortho = sqrtf(fmaxf(2.f - 2.f * dtr / (fro * sqrtf((float)KC)), 0.f));

    // cluster
    float cs = g_cs[w * 32 + l];
    float csn = cs * cs;
#pragma unroll
    for (int o = 16; o; o >>= 1) csn += __shfl_xor_sync(0xffffffffu, csn, o);
    float clus = sqrtf(csn) / (float)NN * sqrtf((float)KC) - 1.f;

    if (l == 0) parts[w] = spec + ortho + clus;
    __syncthreads();
    if (threadIdx.x == 0) {
        float tot = 0.f;
#pragma unroll
        for (int i = 0; i < 16; i++) tot += parts[i];
        outp[NGB * KC * HID] = tot / (float)NGB;   // outp[65536]
    }
}

// ---------------- launch ----------------
extern "C" void kernel_launch(void* const* d_in, const int* in_sizes, int n_in,
                              void* d_out, int out_size) {
    const float *x = 0, *gw = 0, *gb = 0, *gms = 0, *w1 = 0, *b1 = 0, *w2 = 0, *b2 = 0;
    const int *ei = 0;
    int n64 = 0;
    for (int i = 0; i < n_in; i++) {
        int sz = in_sizes[i];
        if (sz == NTT * CIN)       x = (const float*)d_in[i];
        else if (sz == 2 * EDG)    ei = (const int*)d_in[i];
        else if (sz == NTT)        { /* batch, unused (uniform graphs) */ }
        else if (sz == CIN) {
            if (n64 == 0) gw = (const float*)d_in[i];
            else if (n64 == 1) gb = (const float*)d_in[i];
            else gms = (const float*)d_in[i];
            n64++;
        }
        else if (sz == CIN * HID)  w1 = (const float*)d_in[i];
        else if (sz == HID)        b1 = (const float*)d_in[i];
        else if (sz == HID * KC)   w2 = (const float*)d_in[i];
        else if (sz == KC)         b2 = (const float*)d_in[i];
    }
    float* outp = (float*)d_out;
    float* s_out = outp + NGB * KC * HID + 1;   // s at offset 65537

    zero_k<<<256, 256>>>();
    gn_stats_k<<<NGB * 8, 512>>>(x);
    deg_hist_k<<<64, 256>>>(ei);
    scan1_k<<<128, 256>>>();
    scan2_k<<<1, 128>>>();
    scan3_k<<<128, 256>>>();
    hn_k<<<(NTT * 16) / 256, 256>>>(x, gw, gb, gms);
    csr_scatter_k<<<EDG / 256, 256>>>(ei);
    gather_k<<<1024, 256>>>();
    gemm1_k<<<512, 128>>>(w1, b1);
    sm_k<<<512, 256>>>(w2, b2, s_out);
    pool_k<<<NGB * 16, 512>>>();
    trace_k<<<1024, 256>>>();
    out_final_k<<<NGB * KC, 128>>>(outp);
    loss_k<<<1, 512>>>(outp);
}